// round 13
// baseline (speedup 1.0000x reference)
#include <cuda_runtime.h>

// CTC batch cost, two-phase: (1) parallel gather/compaction of the 49 needed
// probability columns into an L2-resident scratch, (2) single-warp linear-
// domain recursion with block-floating-point rescaling reading coalesced
// compact rows. B=128, T=512, C=1024, L=48 -> S=97, blank=1023.
//
// R8 post-mortem: recursion kernel spent ~60-100 cyc/step on L1tex wavefront
// serialization of gathered LDGs (2 loads x ~25 distinct 128B lines, behind
// ONE warp per SM). The gather has no sequential dependency -> hoist it into
// a fully parallel kernel over 148 SMs; the recursion then reads 1 coalesced
// float2 + 1 broadcast float per step (~2-3 wavefronts instead of ~50).
// Rescale max-reduction now uses redux.sync.max.s32 on float bits (alphas
// >= 0 so int compare is order-preserving) -- kills the 5-shfl 130cyc chain.
//
// y_true is int32 (JAX x64 disabled).

#define B_ 128
#define T_ 512
#define C_ 1024
#define L_ 48
#define BLANK_ (C_ - 1)
#define EPS_ 1e-7f
#define LN2_ 0.6931471805599453f
#define KP_ 64      // padded compact row length (48 labels + blank + pad)
#define PD_ 8       // prefetch depth (timesteps)
#define TGT_ 100    // target block exponent after rescale

// 128 * 512 * 64 * 4B = 16.78 MB scratch (static __device__: allowed)
__device__ float g_compact[B_][T_][KP_];

// ---------------- Kernel 1: gather/compact ----------------
// grid (B, 4), block 256. Thread (k = tid&63, t0 = tid>>6) walks 32 t's.
// Stores p + EPS (recursion consumes directly). k>=49 slots get EPS pad.
__global__ __launch_bounds__(256, 4)
void ctc_gather_kernel(const float* __restrict__ y_pred,
                       const int* __restrict__ y_true)
{
    const int b    = blockIdx.x;
    const int tile = blockIdx.y;          // 0..3 -> 128 t's each
    const int tid  = threadIdx.x;
    const int k    = tid & 63;
    const int t0   = tid >> 6;            // 0..3

    const bool valid = (k < 49);
    const int  cls   = (k < 48) ? y_true[b * L_ + k] : BLANK_;
    const float* src = y_pred + (size_t)b * T_ * C_ + cls;

#pragma unroll
    for (int i = 0; i < 32; ++i) {
        const int t = tile * 128 + t0 + i * 4;
        float v = EPS_;
        if (valid) v = src[(size_t)t * C_] + EPS_;
        g_compact[b][t][k] = v;
    }
}

// ---------------- Kernel 2: recursion ----------------
__device__ __forceinline__ int warp_max_bits(float x) {
    int xi = __float_as_int(x);   // x >= 0 -> bit pattern order-preserving
    int r;
    asm("redux.sync.max.s32 %0, %1, 0xffffffff;" : "=r"(r) : "r"(xi));
    return r;
}

__global__ __launch_bounds__(32, 1)
void ctc_loss_kernel(const int* __restrict__ y_true,
                     float* __restrict__ out)
{
    const int b = blockIdx.x;
    const int l = threadIdx.x;      // lane; lanes 25..31 are dummies

    // ---- per-lane skip flags (state 4l+1 -> label 2l, 4l+3 -> 2l+1) ----
    int k1 = min(2 * l,     L_ - 1);
    int k3 = min(2 * l + 1, L_ - 1);
    const int* lab = y_true + b * L_;
    const int cls1 = lab[k1];
    const int cls3 = lab[k3];
    const float skip1f = (l == 0) ? 1.0f : (cls1 != lab[k1 - 1] ? 1.0f : 0.0f);
    const float skip3f = (cls3 != cls1) ? 1.0f : 0.0f;

    const float* cp = &g_compact[b][0][0];   // rows of KP_ floats (256B)

    // ---- t = 0 init (values already have +EPS) ----
    float A0 = 0.0f, A1 = 0.0f, A2 = 0.0f, A3 = 0.0f;
    if (l == 0) { A0 = cp[48]; A1 = cp[0]; }

    // ---- prefetch ring: compact rows t = 1..PD_ ----
    float2 pf[PD_];
    float  pfb[PD_];
#pragma unroll
    for (int j = 0; j < PD_; ++j) {
        int t = min(1 + j, T_ - 1);
        const float* row = cp + (size_t)t * KP_;
        pf[j]  = *(const float2*)(row + 2 * l);
        pfb[j] = row[48];
    }

    float E = 0.0f;       // applied scale: true log2 = log2(A) + E
    int pending_e;        // block exponent measured last boundary
    pending_e = ((warp_max_bits(fmaxf(fmaxf(A0, A1), fmaxf(A2, A3))) >> 23) & 0xFF) - 127;

    // ---- main: 63 superblocks x 8 steps -> t = 1..504 ----
    for (int sb = 0; sb < 63; ++sb) {
        const int tb = 1 + sb * PD_;
#pragma unroll
        for (int u = 0; u < PD_; ++u) {
            if ((u & 3) == 0) {
                // apply pending scale (two multiplies: k may exceed 127)
                int kk = TGT_ - pending_e;
                int ka = kk >> 1, kb = kk - ka;
                float fa = __int_as_float((ka + 127) << 23);
                float fb = __int_as_float((kb + 127) << 23);
                A0 *= fa; A1 *= fa; A2 *= fa; A3 *= fa;
                A0 *= fb; A1 *= fb; A2 *= fb; A3 *= fb;
                E -= (float)kk;
                // measure for NEXT window (stale-by-4 is fine: any common
                // scale is correct; drift bound 2^-186 from 2^100 is safe)
                float m = fmaxf(fmaxf(A0, A1), fmaxf(A2, A3));
                pending_e = ((warp_max_bits(m) >> 23) & 0xFF) - 127;
            }

            const int t = tb + u;
            const float2 p  = pf[u];
            const float  pb = pfb[u];

            // re-issue row load PD_ steps ahead (clamped at tail)
            int tn = min(t + PD_, T_ - 1);
            const float* row = cp + (size_t)tn * KP_;
            pf[u]  = *(const float2*)(row + 2 * l);
            pfb[u] = row[48];

            float n3 = __shfl_up_sync(0xffffffffu, A3, 1);
            if (l == 0) n3 = 0.0f;

            float A0n = (A0 + n3) * pb;
            float A1n = fmaf(skip1f, n3, A1 + A0) * p.x;
            float A2n = (A2 + A1) * pb;
            float A3n = fmaf(skip3f, A1, A3 + A2) * p.y;
            A0 = A0n; A1 = A1n; A2 = A2n; A3 = A3n;
        }
    }

    // ---- tail: t = 505..511 (ring slots j = 0..6 hold them) ----
#pragma unroll
    for (int j = 0; j < 7; ++j) {
        if ((j & 3) == 0) {
            int kk = TGT_ - pending_e;
            int ka = kk >> 1, kb = kk - ka;
            float fa = __int_as_float((ka + 127) << 23);
            float fb = __int_as_float((kb + 127) << 23);
            A0 *= fa; A1 *= fa; A2 *= fa; A3 *= fa;
            A0 *= fb; A1 *= fb; A2 *= fb; A3 *= fb;
            E -= (float)kk;
            float m = fmaxf(fmaxf(A0, A1), fmaxf(A2, A3));
            pending_e = ((warp_max_bits(m) >> 23) & 0xFF) - 127;
        }
        const float2 p  = pf[j];
        const float  pb = pfb[j];
        float n3 = __shfl_up_sync(0xffffffffu, A3, 1);
        if (l == 0) n3 = 0.0f;
        float A0n = (A0 + n3) * pb;
        float A1n = fmaf(skip1f, n3, A1 + A0) * p.x;
        float A2n = (A2 + A1) * pb;
        float A3n = fmaf(skip3f, A1, A3 + A2) * p.y;
        A0 = A0n; A1 = A1n; A2 = A2n; A3 = A3n;
    }

    // ---- loss = -ln2 * (log2(a96 + a95) + E) ----
    float a96 = __shfl_sync(0xffffffffu, A0, 24);   // state 96
    float a95 = __shfl_sync(0xffffffffu, A3, 23);   // state 95
    if (l == 0) {
        out[b] = -((log2f(a96 + a95) + E) * LN2_);
    }
}

extern "C" void kernel_launch(void* const* d_in, const int* in_sizes, int n_in,
                              void* d_out, int out_size)
{
    const float* y_pred = (const float*)d_in[0];   // [B, T, C] f32
    const int*   y_true = (const int*)d_in[1];     // [B, L] int32
    float*       out    = (float*)d_out;           // [B, 1] f32

    dim3 g1(B_, 4);
    ctc_gather_kernel<<<g1, 256>>>(y_pred, y_true);
    ctc_loss_kernel<<<B_, 32>>>(y_true, out);
}